// round 1
// baseline (speedup 1.0000x reference)
#include <cuda_runtime.h>
#include <cuda_bf16.h>
#include <math.h>

// SpatialNCA: h[N,128], pos[N,2], edges E=500000.
// Pipeline:
//  P = h@Wm1_top, Q = h@Wm1_mid           (node GEMMs)
//  X1[e] = P[dst]+Q[src]+dist*w_last+bm1  (edge assembly, store diff)
//  stats(X1) -> bn1;  X2 = bn_relu1(X1)@Wm2+bm2
//  stats(X2) -> bn2;  S  = bn_relu2(X2)@Wp1+bp1
//  stats(S)  -> bn3;  sp = bn_relu3(S)·Wp2+bp2
//  stats(sp) -> bn4
//  aggregate: h_aggr[dst]+=bn_relu2(X2[e]); possum[dst]+=diff*bn_relu4(sp); cnt
//  U = [h|h_aggr]@Wu1+bu1; stats(U)->bn5
//  out_h = h + bn_relu5(U); out_pos = pos + possum/max(cnt,1)

#define NN 50000
#define EE 500000
#define BN_EPS 1e-5f

__device__ float g_P[NN * 128];
__device__ float g_Q[NN * 128];
__device__ float g_X1[EE * 128];
__device__ float g_X2[EE * 128];
__device__ float g_S[EE * 128];
__device__ float g_diff[EE * 2];
__device__ float g_sp[EE];
__device__ float g_haggr[NN * 128];
__device__ float g_possum[NN * 2];
__device__ float g_cnt[NN];
__device__ float g_U[NN * 128];
__device__ double g_sum[5 * 128];
__device__ double g_sumsq[5 * 128];
__device__ float g_acta[5 * 128];
__device__ float g_actc[5 * 128];

__device__ __forceinline__ void red_add_v4(float* p, float4 v) {
    asm volatile("red.global.add.v4.f32 [%0], {%1,%2,%3,%4};"
                 :: "l"(p), "f"(v.x), "f"(v.y), "f"(v.z), "f"(v.w) : "memory");
}
__device__ __forceinline__ void red_add_v2(float* p, float2 v) {
    asm volatile("red.global.add.v2.f32 [%0], {%1,%2};"
                 :: "l"(p), "f"(v.x), "f"(v.y) : "memory");
}

// ---------------- zero scratch ----------------
__global__ void k_zero() {
    int idx = blockIdx.x * blockDim.x + threadIdx.x;
    int stride = gridDim.x * blockDim.x;
    for (int i = idx; i < NN * 128; i += stride) g_haggr[i] = 0.f;
    for (int i = idx; i < NN * 2; i += stride) g_possum[i] = 0.f;
    for (int i = idx; i < NN; i += stride) g_cnt[i] = 0.f;
    if (idx < 5 * 128) { g_sum[idx] = 0.0; g_sumsq[idx] = 0.0; }
}

// ---------------- generic GEMM: C[rows,128] = act(A[rows,128]) @ W[128,128] + bias ----------------
// act(x) = relu(x*acta[c]+actc[c]) if acta!=null, else identity.
__global__ __launch_bounds__(256) void k_gemm128(
    const float* __restrict__ A, const float* __restrict__ W,
    const float* __restrict__ bias,
    const float* __restrict__ acta, const float* __restrict__ actc,
    float* __restrict__ C, int rows)
{
    __shared__ float As[64][20];
    __shared__ float Ws[16][132];
    int tid = threadIdx.x;
    int tx = tid & 15, ty = tid >> 4;
    int r0 = blockIdx.x * 64;

    float acc[4][8];
#pragma unroll
    for (int i = 0; i < 4; i++)
#pragma unroll
        for (int j = 0; j < 8; j++) acc[i][j] = 0.f;

    int le = tid >> 2;       // 0..63 : A row within tile
    int lm = tid & 3;        // 0..3  : k-quad within chunk
    int arow = r0 + le;
    int wk = tid >> 4;       // 0..15 : W row within chunk
    int wc = (tid & 15) * 8; // col

    for (int kc = 0; kc < 128; kc += 16) {
        float4 av = make_float4(0.f, 0.f, 0.f, 0.f);
        if (arow < rows) {
            av = *(const float4*)(A + (size_t)arow * 128 + kc + lm * 4);
            if (acta) {
                int c = kc + lm * 4;
                av.x = fmaxf(fmaf(av.x, acta[c + 0], actc[c + 0]), 0.f);
                av.y = fmaxf(fmaf(av.y, acta[c + 1], actc[c + 1]), 0.f);
                av.z = fmaxf(fmaf(av.z, acta[c + 2], actc[c + 2]), 0.f);
                av.w = fmaxf(fmaf(av.w, acta[c + 3], actc[c + 3]), 0.f);
            }
        }
        As[le][lm * 4 + 0] = av.x;
        As[le][lm * 4 + 1] = av.y;
        As[le][lm * 4 + 2] = av.z;
        As[le][lm * 4 + 3] = av.w;

        float4 w0 = *(const float4*)(W + (size_t)(kc + wk) * 128 + wc);
        float4 w1 = *(const float4*)(W + (size_t)(kc + wk) * 128 + wc + 4);
        *(float4*)&Ws[wk][wc] = w0;
        *(float4*)&Ws[wk][wc + 4] = w1;
        __syncthreads();

#pragma unroll
        for (int kk = 0; kk < 16; kk++) {
            float4 b0 = *(const float4*)&Ws[kk][tx * 8];
            float4 b1 = *(const float4*)&Ws[kk][tx * 8 + 4];
            float a[4];
#pragma unroll
            for (int i = 0; i < 4; i++) a[i] = As[ty * 4 + i][kk];
#pragma unroll
            for (int i = 0; i < 4; i++) {
                acc[i][0] = fmaf(a[i], b0.x, acc[i][0]);
                acc[i][1] = fmaf(a[i], b0.y, acc[i][1]);
                acc[i][2] = fmaf(a[i], b0.z, acc[i][2]);
                acc[i][3] = fmaf(a[i], b0.w, acc[i][3]);
                acc[i][4] = fmaf(a[i], b1.x, acc[i][4]);
                acc[i][5] = fmaf(a[i], b1.y, acc[i][5]);
                acc[i][6] = fmaf(a[i], b1.z, acc[i][6]);
                acc[i][7] = fmaf(a[i], b1.w, acc[i][7]);
            }
        }
        __syncthreads();
    }

    float bz[8] = {0.f, 0.f, 0.f, 0.f, 0.f, 0.f, 0.f, 0.f};
    if (bias) {
        float4 b0 = *(const float4*)(bias + tx * 8);
        float4 b1 = *(const float4*)(bias + tx * 8 + 4);
        bz[0] = b0.x; bz[1] = b0.y; bz[2] = b0.z; bz[3] = b0.w;
        bz[4] = b1.x; bz[5] = b1.y; bz[6] = b1.z; bz[7] = b1.w;
    }
#pragma unroll
    for (int i = 0; i < 4; i++) {
        int r = r0 + ty * 4 + i;
        if (r < rows) {
            float4 o0 = make_float4(acc[i][0] + bz[0], acc[i][1] + bz[1],
                                    acc[i][2] + bz[2], acc[i][3] + bz[3]);
            float4 o1 = make_float4(acc[i][4] + bz[4], acc[i][5] + bz[5],
                                    acc[i][6] + bz[6], acc[i][7] + bz[7]);
            *(float4*)(C + (size_t)r * 128 + tx * 8) = o0;
            *(float4*)(C + (size_t)r * 128 + tx * 8 + 4) = o1;
        }
    }
}

// ---------------- update GEMM: C[rows,128] = [A1|A2] @ W[256,128] + bias ----------------
__global__ __launch_bounds__(256) void k_gemm_upd(
    const float* __restrict__ A1, const float* __restrict__ A2,
    const float* __restrict__ W, const float* __restrict__ bias,
    float* __restrict__ C, int rows)
{
    __shared__ float As[64][20];
    __shared__ float Ws[16][132];
    int tid = threadIdx.x;
    int tx = tid & 15, ty = tid >> 4;
    int r0 = blockIdx.x * 64;

    float acc[4][8];
#pragma unroll
    for (int i = 0; i < 4; i++)
#pragma unroll
        for (int j = 0; j < 8; j++) acc[i][j] = 0.f;

    int le = tid >> 2;
    int lm = tid & 3;
    int arow = r0 + le;
    int wk = tid >> 4;
    int wc = (tid & 15) * 8;

    for (int kc = 0; kc < 256; kc += 16) {
        const float* Asrc = (kc < 128) ? A1 : A2;
        int colbase = (kc & 127) + lm * 4;
        float4 av = make_float4(0.f, 0.f, 0.f, 0.f);
        if (arow < rows)
            av = *(const float4*)(Asrc + (size_t)arow * 128 + colbase);
        As[le][lm * 4 + 0] = av.x;
        As[le][lm * 4 + 1] = av.y;
        As[le][lm * 4 + 2] = av.z;
        As[le][lm * 4 + 3] = av.w;

        float4 w0 = *(const float4*)(W + (size_t)(kc + wk) * 128 + wc);
        float4 w1 = *(const float4*)(W + (size_t)(kc + wk) * 128 + wc + 4);
        *(float4*)&Ws[wk][wc] = w0;
        *(float4*)&Ws[wk][wc + 4] = w1;
        __syncthreads();

#pragma unroll
        for (int kk = 0; kk < 16; kk++) {
            float4 b0 = *(const float4*)&Ws[kk][tx * 8];
            float4 b1 = *(const float4*)&Ws[kk][tx * 8 + 4];
            float a[4];
#pragma unroll
            for (int i = 0; i < 4; i++) a[i] = As[ty * 4 + i][kk];
#pragma unroll
            for (int i = 0; i < 4; i++) {
                acc[i][0] = fmaf(a[i], b0.x, acc[i][0]);
                acc[i][1] = fmaf(a[i], b0.y, acc[i][1]);
                acc[i][2] = fmaf(a[i], b0.z, acc[i][2]);
                acc[i][3] = fmaf(a[i], b0.w, acc[i][3]);
                acc[i][4] = fmaf(a[i], b1.x, acc[i][4]);
                acc[i][5] = fmaf(a[i], b1.y, acc[i][5]);
                acc[i][6] = fmaf(a[i], b1.z, acc[i][6]);
                acc[i][7] = fmaf(a[i], b1.w, acc[i][7]);
            }
        }
        __syncthreads();
    }

    float4 b0 = *(const float4*)(bias + tx * 8);
    float4 b1 = *(const float4*)(bias + tx * 8 + 4);
    float bz[8] = {b0.x, b0.y, b0.z, b0.w, b1.x, b1.y, b1.z, b1.w};
#pragma unroll
    for (int i = 0; i < 4; i++) {
        int r = r0 + ty * 4 + i;
        if (r < rows) {
            float4 o0 = make_float4(acc[i][0] + bz[0], acc[i][1] + bz[1],
                                    acc[i][2] + bz[2], acc[i][3] + bz[3]);
            float4 o1 = make_float4(acc[i][4] + bz[4], acc[i][5] + bz[5],
                                    acc[i][6] + bz[6], acc[i][7] + bz[7]);
            *(float4*)(C + (size_t)r * 128 + tx * 8) = o0;
            *(float4*)(C + (size_t)r * 128 + tx * 8 + 4) = o1;
        }
    }
}

// ---------------- edge assembly: X1[e] = P[dst]+Q[src]+dist*w_last+bm1 ----------------
__global__ void k_edges(const int* __restrict__ src, const int* __restrict__ dst,
                        const float* __restrict__ pos,
                        const float* __restrict__ Wm1, const float* __restrict__ bm1)
{
    int e = (blockIdx.x * blockDim.x + threadIdx.x) >> 5;
    int lane = threadIdx.x & 31;
    if (e >= EE) return;
    int s = src[e], d = dst[e];
    float2 ps = ((const float2*)pos)[s];
    float2 pd = ((const float2*)pos)[d];
    float dx = ps.x - pd.x, dy = ps.y - pd.y;
    float dist = sqrtf(dx * dx + dy * dy);
    if (lane == 0) ((float2*)g_diff)[e] = make_float2(dx, dy);
    int c = lane * 4;
    float4 p = *(const float4*)(g_P + (size_t)d * 128 + c);
    float4 q = *(const float4*)(g_Q + (size_t)s * 128 + c);
    float4 w = *(const float4*)(Wm1 + 256 * 128 + c);
    float4 b = *(const float4*)(bm1 + c);
    float4 x;
    x.x = p.x + q.x + dist * w.x + b.x;
    x.y = p.y + q.y + dist * w.y + b.y;
    x.z = p.z + q.z + dist * w.z + b.z;
    x.w = p.w + q.w + dist * w.w + b.w;
    *(float4*)(g_X1 + (size_t)e * 128 + c) = x;
}

// ---------------- per-column stats over [rows,128] ----------------
__global__ void k_stats(const float* __restrict__ X, int rows,
                        double* __restrict__ sum, double* __restrict__ sumsq)
{
    int c = threadIdx.x & 127;
    int half = threadIdx.x >> 7;
    double s = 0.0, ss = 0.0;
    for (int r = blockIdx.x * 2 + half; r < rows; r += gridDim.x * 2) {
        float v = X[(size_t)r * 128 + c];
        s += v;
        ss += (double)v * (double)v;
    }
    __shared__ double sb[256], ssb[256];
    sb[threadIdx.x] = s; ssb[threadIdx.x] = ss;
    __syncthreads();
    if (threadIdx.x < 128) {
        atomicAdd(&sum[c], sb[threadIdx.x] + sb[threadIdx.x + 128]);
        atomicAdd(&sumsq[c], ssb[threadIdx.x] + ssb[threadIdx.x + 128]);
    }
}

// ---------------- scalar stats ----------------
__global__ void k_stats1(const float* __restrict__ X, int n,
                         double* __restrict__ sum, double* __restrict__ sumsq)
{
    double s = 0.0, ss = 0.0;
    for (int i = blockIdx.x * blockDim.x + threadIdx.x; i < n; i += gridDim.x * blockDim.x) {
        float v = X[i];
        s += v;
        ss += (double)v * (double)v;
    }
    __shared__ double sb[256], ssb[256];
    sb[threadIdx.x] = s; ssb[threadIdx.x] = ss;
    __syncthreads();
    for (int o = 128; o > 0; o >>= 1) {
        if (threadIdx.x < o) {
            sb[threadIdx.x] += sb[threadIdx.x + o];
            ssb[threadIdx.x] += ssb[threadIdx.x + o];
        }
        __syncthreads();
    }
    if (threadIdx.x == 0) {
        atomicAdd(&sum[0], sb[0]);
        atomicAdd(&sumsq[0], ssb[0]);
    }
}

// ---------------- finalize BN affine: a = g*rstd, c = bb - mean*a ----------------
__global__ void k_fin(const double* __restrict__ sum, const double* __restrict__ sumsq,
                      const float* __restrict__ g, const float* __restrict__ bb,
                      float* __restrict__ acta, float* __restrict__ actc,
                      int rows, int ncols)
{
    int c = threadIdx.x;
    if (c < ncols) {
        double m = sum[c] / rows;
        double v = sumsq[c] / rows - m * m;
        float rstd = rsqrtf((float)v + BN_EPS);
        float a = g[c] * rstd;
        acta[c] = a;
        actc[c] = bb[c] - (float)m * a;
    }
}

// ---------------- gemv: sp[e] = bn_relu3(S[e]) . Wp2 + bp2 ----------------
__global__ void k_gemv(const float* __restrict__ S, const float* __restrict__ Wp2,
                       const float* __restrict__ bp2,
                       const float* __restrict__ acta, const float* __restrict__ actc,
                       float* __restrict__ out)
{
    int e = (blockIdx.x * blockDim.x + threadIdx.x) >> 5;
    int lane = threadIdx.x & 31;
    if (e >= EE) return;
    int c = lane * 4;
    float4 sv = *(const float4*)(S + (size_t)e * 128 + c);
    float4 wv = *(const float4*)(Wp2 + c);
    float d = fmaxf(fmaf(sv.x, acta[c + 0], actc[c + 0]), 0.f) * wv.x
            + fmaxf(fmaf(sv.y, acta[c + 1], actc[c + 1]), 0.f) * wv.y
            + fmaxf(fmaf(sv.z, acta[c + 2], actc[c + 2]), 0.f) * wv.z
            + fmaxf(fmaf(sv.w, acta[c + 3], actc[c + 3]), 0.f) * wv.w;
#pragma unroll
    for (int o = 16; o > 0; o >>= 1) d += __shfl_down_sync(0xffffffffu, d, o);
    if (lane == 0) out[e] = d + bp2[0];
}

// ---------------- aggregation ----------------
__global__ void k_aggr(const int* __restrict__ dst,
                       const float* __restrict__ acta2, const float* __restrict__ actc2,
                       const float* __restrict__ a4, const float* __restrict__ c4)
{
    int e = (blockIdx.x * blockDim.x + threadIdx.x) >> 5;
    int lane = threadIdx.x & 31;
    if (e >= EE) return;
    int d = dst[e];
    int c = lane * 4;
    float4 x = *(const float4*)(g_X2 + (size_t)e * 128 + c);
    float4 m;
    m.x = fmaxf(fmaf(x.x, acta2[c + 0], actc2[c + 0]), 0.f);
    m.y = fmaxf(fmaf(x.y, acta2[c + 1], actc2[c + 1]), 0.f);
    m.z = fmaxf(fmaf(x.z, acta2[c + 2], actc2[c + 2]), 0.f);
    m.w = fmaxf(fmaf(x.w, acta2[c + 3], actc2[c + 3]), 0.f);
    red_add_v4(g_haggr + (size_t)d * 128 + c, m);
    if (lane == 0) {
        float sp = g_sp[e];
        float sc = fmaxf(fmaf(sp, a4[0], c4[0]), 0.f);
        float2 df = ((const float2*)g_diff)[e];
        red_add_v2(g_possum + 2 * (size_t)d, make_float2(df.x * sc, df.y * sc));
        atomicAdd(&g_cnt[d], 1.f);
    }
}

// ---------------- final residual write ----------------
__global__ void k_final(const float* __restrict__ h, const float* __restrict__ pos,
                        const float* __restrict__ a5, const float* __restrict__ c5,
                        float* __restrict__ out)
{
    int i = blockIdx.x * blockDim.x + threadIdx.x;
    if (i < NN * 128) {
        int c = i & 127;
        float u = g_U[i];
        out[i] = h[i] + fmaxf(fmaf(u, a5[c], c5[c]), 0.f);
    }
    if (i < NN) {
        float cnt = fmaxf(g_cnt[i], 1.f);
        out[NN * 128 + 2 * i + 0] = pos[2 * i + 0] + g_possum[2 * i + 0] / cnt;
        out[NN * 128 + 2 * i + 1] = pos[2 * i + 1] + g_possum[2 * i + 1] / cnt;
    }
}

extern "C" void kernel_launch(void* const* d_in, const int* in_sizes, int n_in,
                              void* d_out, int out_size)
{
    const float* h    = (const float*)d_in[0];
    const float* pos  = (const float*)d_in[1];
    const int*   ei   = (const int*)d_in[3];
    const int*   src  = ei;
    const int*   dst  = ei + EE;
    const float* Wm1  = (const float*)d_in[4];
    const float* bm1  = (const float*)d_in[5];
    const float* gm1  = (const float*)d_in[6];
    const float* bbm1 = (const float*)d_in[7];
    const float* Wm2  = (const float*)d_in[8];
    const float* bm2  = (const float*)d_in[9];
    const float* gm2  = (const float*)d_in[10];
    const float* bbm2 = (const float*)d_in[11];
    const float* Wp1  = (const float*)d_in[12];
    const float* bp1  = (const float*)d_in[13];
    const float* gp1  = (const float*)d_in[14];
    const float* bbp1 = (const float*)d_in[15];
    const float* Wp2  = (const float*)d_in[16];
    const float* bp2  = (const float*)d_in[17];
    const float* gp2  = (const float*)d_in[18];
    const float* bbp2 = (const float*)d_in[19];
    const float* Wu1  = (const float*)d_in[20];
    const float* bu1  = (const float*)d_in[21];
    const float* gu1  = (const float*)d_in[22];
    const float* bbu1 = (const float*)d_in[23];
    float* out = (float*)d_out;

    void* p;
    cudaGetSymbolAddress(&p, g_P);      float* P    = (float*)p;
    cudaGetSymbolAddress(&p, g_Q);      float* Q    = (float*)p;
    cudaGetSymbolAddress(&p, g_X1);     float* X1   = (float*)p;
    cudaGetSymbolAddress(&p, g_X2);     float* X2   = (float*)p;
    cudaGetSymbolAddress(&p, g_S);      float* S    = (float*)p;
    cudaGetSymbolAddress(&p, g_sp);     float* SP   = (float*)p;
    cudaGetSymbolAddress(&p, g_haggr);  float* HAGG = (float*)p;
    cudaGetSymbolAddress(&p, g_U);      float* U    = (float*)p;
    cudaGetSymbolAddress(&p, g_sum);    double* SUM = (double*)p;
    cudaGetSymbolAddress(&p, g_sumsq);  double* SSQ = (double*)p;
    cudaGetSymbolAddress(&p, g_acta);   float* ACTA = (float*)p;
    cudaGetSymbolAddress(&p, g_actc);   float* ACTC = (float*)p;

    const int GEMM_E_BLOCKS = (EE + 63) / 64;   // 7813
    const int GEMM_N_BLOCKS = (NN + 63) / 64;   // 782
    const int WARP_E_BLOCKS = EE / 8;           // 62500 (256 thr = 8 warps)

    k_zero<<<2048, 256>>>();

    // node GEMMs for message layer 1 factorization
    k_gemm128<<<GEMM_N_BLOCKS, 256>>>(h, Wm1, nullptr, nullptr, nullptr, P, NN);
    k_gemm128<<<GEMM_N_BLOCKS, 256>>>(h, Wm1 + 128 * 128, nullptr, nullptr, nullptr, Q, NN);

    // edge assembly
    k_edges<<<WARP_E_BLOCKS, 256>>>(src, dst, pos, Wm1, bm1);

    // BN1 stats + msg layer 2
    k_stats<<<2048, 256>>>(X1, EE, SUM + 0, SSQ + 0);
    k_fin<<<1, 128>>>(SUM + 0, SSQ + 0, gm1, bbm1, ACTA + 0, ACTC + 0, EE, 128);
    k_gemm128<<<GEMM_E_BLOCKS, 256>>>(X1, Wm2, bm2, ACTA + 0, ACTC + 0, X2, EE);

    // BN2 stats + pos layer 1
    k_stats<<<2048, 256>>>(X2, EE, SUM + 128, SSQ + 128);
    k_fin<<<1, 128>>>(SUM + 128, SSQ + 128, gm2, bbm2, ACTA + 128, ACTC + 128, EE, 128);
    k_gemm128<<<GEMM_E_BLOCKS, 256>>>(X2, Wp1, bp1, ACTA + 128, ACTC + 128, S, EE);

    // BN3 stats + pos layer 2 (gemv)
    k_stats<<<2048, 256>>>(S, EE, SUM + 256, SSQ + 256);
    k_fin<<<1, 128>>>(SUM + 256, SSQ + 256, gp1, bbp1, ACTA + 256, ACTC + 256, EE, 128);
    k_gemv<<<WARP_E_BLOCKS, 256>>>(S, Wp2, bp2, ACTA + 256, ACTC + 256, SP);

    // BN4 stats (scalar)
    k_stats1<<<1024, 256>>>(SP, EE, SUM + 384, SSQ + 384);
    k_fin<<<1, 128>>>(SUM + 384, SSQ + 384, gp2, bbp2, ACTA + 384, ACTC + 384, EE, 1);

    // aggregation
    k_aggr<<<WARP_E_BLOCKS, 256>>>(dst, ACTA + 128, ACTC + 128, ACTA + 384, ACTC + 384);

    // update MLP
    k_gemm_upd<<<GEMM_N_BLOCKS, 256>>>(h, HAGG, Wu1, bu1, U, NN);
    k_stats<<<2048, 256>>>(U, NN, SUM + 512, SSQ + 512);
    k_fin<<<1, 128>>>(SUM + 512, SSQ + 512, gu1, bbu1, ACTA + 512, ACTC + 512, NN, 128);

    // residual outputs
    k_final<<<(NN * 128 + 255) / 256, 256>>>(h, pos, ACTA + 512, ACTC + 512, out);
}

// round 2
// speedup vs baseline: 1.9027x; 1.9027x over previous
#include <cuda_runtime.h>
#include <cuda_bf16.h>
#include <math.h>

#define NN 50000
#define EE 500000
#define BN_EPS 1e-5f

// ---------------- global scratch ----------------
__device__ float g_PQ[NN * 256];          // [n][0:128]=P, [128:256]=Q
__device__ float g_X2[(size_t)EE * 128];
__device__ float g_S[(size_t)EE * 128];
__device__ float g_diff[EE * 2];
__device__ float g_dist[EE];
__device__ float g_sp[EE];
__device__ float g_haggr[NN * 128];
__device__ float g_possum[NN * 2];
__device__ float g_cnt[NN];
__device__ float g_U[NN * 128];
__device__ double g_sum[5 * 128];
__device__ double g_sumsq[5 * 128];
__device__ float g_acta[5 * 128];
__device__ float g_actc[5 * 128];
// transposed bf16 hi/lo weights: WT[n][k]
__device__ __nv_bfloat16 g_wtpq_h[256 * 128], g_wtpq_l[256 * 128];
__device__ __nv_bfloat16 g_wtm2_h[128 * 128], g_wtm2_l[128 * 128];
__device__ __nv_bfloat16 g_wtp1_h[128 * 128], g_wtp1_l[128 * 128];
__device__ __nv_bfloat16 g_wtu_h[128 * 256], g_wtu_l[128 * 256];

__device__ __forceinline__ void red_add_v4(float* p, float4 v) {
    asm volatile("red.global.add.v4.f32 [%0], {%1,%2,%3,%4};"
                 :: "l"(p), "f"(v.x), "f"(v.y), "f"(v.z), "f"(v.w) : "memory");
}
__device__ __forceinline__ void red_add_v2(float* p, float2 v) {
    asm volatile("red.global.add.v2.f32 [%0], {%1,%2};"
                 :: "l"(p), "f"(v.x), "f"(v.y) : "memory");
}
__device__ __forceinline__ unsigned pkbf(__nv_bfloat16 a, __nv_bfloat16 b) {
    unsigned lo = __bfloat16_as_ushort(a);
    unsigned hi = __bfloat16_as_ushort(b);
    return (hi << 16) | lo;
}
__device__ __forceinline__ void split1(float x, __nv_bfloat16& h, __nv_bfloat16& l) {
    h = __float2bfloat16(x);
    l = __float2bfloat16(x - __bfloat162float(h));
}
__device__ __forceinline__ void mma_bf16(float* d, const unsigned* a, unsigned b0, unsigned b1) {
    asm volatile("mma.sync.aligned.m16n8k16.row.col.f32.bf16.bf16.f32 "
                 "{%0,%1,%2,%3},{%4,%5,%6,%7},{%8,%9},{%0,%1,%2,%3};"
                 : "+f"(d[0]), "+f"(d[1]), "+f"(d[2]), "+f"(d[3])
                 : "r"(a[0]), "r"(a[1]), "r"(a[2]), "r"(a[3]), "r"(b0), "r"(b1));
}

// ---------------- zero scratch ----------------
__global__ void k_zero() {
    int idx = blockIdx.x * blockDim.x + threadIdx.x;
    int stride = gridDim.x * blockDim.x;
    for (int i = idx; i < NN * 128; i += stride) g_haggr[i] = 0.f;
    for (int i = idx; i < NN * 2; i += stride) g_possum[i] = 0.f;
    for (int i = idx; i < NN; i += stride) g_cnt[i] = 0.f;
    if (idx < 5 * 128) { g_sum[idx] = 0.0; g_sumsq[idx] = 0.0; }
}

// ---------------- weight prep: transpose + bf16 hi/lo split ----------------
__global__ void k_prepw(const float* __restrict__ Wm1, const float* __restrict__ Wm2,
                        const float* __restrict__ Wp1, const float* __restrict__ Wu1)
{
    int idx = blockIdx.x * blockDim.x + threadIdx.x;
    int stride = gridDim.x * blockDim.x;
    for (int i = idx; i < 256 * 128; i += stride) {
        int n = i >> 7, k = i & 127;
        float v = (n < 128) ? Wm1[k * 128 + n] : Wm1[(128 + k) * 128 + (n - 128)];
        split1(v, g_wtpq_h[i], g_wtpq_l[i]);
    }
    for (int i = idx; i < 128 * 128; i += stride) {
        int n = i >> 7, k = i & 127;
        split1(Wm2[k * 128 + n], g_wtm2_h[i], g_wtm2_l[i]);
        split1(Wp1[k * 128 + n], g_wtp1_h[i], g_wtp1_l[i]);
    }
    for (int i = idx; i < 128 * 256; i += stride) {
        int n = i >> 8, k = i & 255;
        split1(Wu1[k * 128 + n], g_wtu_h[i], g_wtu_l[i]);
    }
}

// ---------------- tensor-core GEMM ----------------
// C[rows, ncols] = act(A[rows, kTotal]) @ W[kTotal, ncols] + bias
// AMODE: 0 = plain fp32 A; 1 = concat [A|A2] (kTotal=256); 2 = edge-assembled A
// BN: apply relu(x*acta+actc) to A columns before use (K must be 128)
// STATS: accumulate per-output-column sum/sumsq (grid.y must be 1)
// AGGR: red.add the (post-BN) A values to aggrOut[dst[row]*128 + col]
template<int AMODE, bool BN, bool STATS, bool AGGR>
__global__ __launch_bounds__(256) void k_gemm_tc(
    const float* __restrict__ A, const float* __restrict__ A2,
    const __nv_bfloat16* __restrict__ WTh, const __nv_bfloat16* __restrict__ WTl,
    const float* __restrict__ bias,
    const float* __restrict__ acta, const float* __restrict__ actc,
    float* __restrict__ C, int rows, int kTotal, int ldC,
    const int* __restrict__ srcIdx, const int* __restrict__ dstIdx,
    const float* __restrict__ dist,
    const float* __restrict__ wlast, const float* __restrict__ bm1v,
    double* __restrict__ sumOut, double* __restrict__ sumsqOut,
    float* __restrict__ aggrOut)
{
    __shared__ __nv_bfloat16 Ah[128 * 40];
    __shared__ __nv_bfloat16 Al[128 * 40];
    __shared__ __nv_bfloat16 Wh[128 * 40];
    __shared__ __nv_bfloat16 Wl[128 * 40];

    const int t = threadIdx.x;
    const int rowBase = blockIdx.x * 128;
    const int ncolBase = blockIdx.y * 128;

    float acc[2][8][4];
#pragma unroll
    for (int i = 0; i < 2; i++)
#pragma unroll
        for (int j = 0; j < 8; j++)
#pragma unroll
            for (int k = 0; k < 4; k++) acc[i][j][k] = 0.f;

    const int w = t >> 5, l = t & 31;
    const int m0 = (w >> 1) * 32, n0 = (w & 1) * 64;
    const int lr = l >> 2, lc = 2 * (l & 3);

    // A-fill indexing: 2 threads per row, row = t>>1
    const int rl = t >> 1;
    const int grow = rowBase + rl;
    const bool valid = grow < rows;
    int ed = 0, es = 0;
    float de = 0.f;
    if ((AMODE == 2 || AGGR) && valid) ed = dstIdx[grow];
    if (AMODE == 2 && valid) { es = srcIdx[grow]; de = dist[grow]; }

    for (int kc = 0; kc < kTotal; kc += 32) {
        __syncthreads();
        // ---- A chunk fill: 128 rows x 32 cols ----
#pragma unroll
        for (int j = 0; j < 4; j++) {
            int cl = 4 * (t & 1) + 8 * j;   // 0..28
            int cg = kc + cl;
            float4 v = make_float4(0.f, 0.f, 0.f, 0.f);
            if (valid) {
                if (AMODE == 0) {
                    v = *(const float4*)(A + (size_t)grow * kTotal + cg);
                } else if (AMODE == 1) {
                    const float* Asrc = (cg < 128) ? A : A2;
                    v = *(const float4*)(Asrc + (size_t)grow * 128 + (cg & 127));
                } else { // ASSEMBLE
                    float4 p = *(const float4*)(g_PQ + (size_t)ed * 256 + cg);
                    float4 q = *(const float4*)(g_PQ + (size_t)es * 256 + 128 + cg);
                    float4 wv = *(const float4*)(wlast + cg);
                    float4 bv = *(const float4*)(bm1v + cg);
                    v.x = p.x + q.x + de * wv.x + bv.x;
                    v.y = p.y + q.y + de * wv.y + bv.y;
                    v.z = p.z + q.z + de * wv.z + bv.z;
                    v.w = p.w + q.w + de * wv.w + bv.w;
                }
                if (BN) {
                    v.x = fmaxf(fmaf(v.x, acta[cg + 0], actc[cg + 0]), 0.f);
                    v.y = fmaxf(fmaf(v.y, acta[cg + 1], actc[cg + 1]), 0.f);
                    v.z = fmaxf(fmaf(v.z, acta[cg + 2], actc[cg + 2]), 0.f);
                    v.w = fmaxf(fmaf(v.w, acta[cg + 3], actc[cg + 3]), 0.f);
                }
                if (AGGR) red_add_v4(aggrOut + (size_t)ed * 128 + cg, v);
            }
            __nv_bfloat16 h0, h1, h2, h3, l0, l1, l2, l3;
            split1(v.x, h0, l0); split1(v.y, h1, l1);
            split1(v.z, h2, l2); split1(v.w, h3, l3);
            *(uint2*)(Ah + rl * 40 + cl) = make_uint2(pkbf(h0, h1), pkbf(h2, h3));
            *(uint2*)(Al + rl * 40 + cl) = make_uint2(pkbf(l0, l1), pkbf(l2, l3));
        }
        // ---- W chunk fill: 128 n-rows x 32 k ----
        {
            int n = t >> 1;
#pragma unroll
            for (int j = 0; j < 2; j++) {
                int k8 = (t & 1) + 2 * j;  // uint4 index: 0..3
                size_t gi = (size_t)(ncolBase + n) * kTotal + kc + k8 * 8;
                *(uint4*)(Wh + n * 40 + k8 * 8) = *(const uint4*)(WTh + gi);
                *(uint4*)(Wl + n * 40 + k8 * 8) = *(const uint4*)(WTl + gi);
            }
        }
        __syncthreads();

        // ---- MMA over 2 k-steps of 16 ----
#pragma unroll
        for (int ks = 0; ks < 2; ks++) {
            int kb = ks * 16;
            unsigned ah[2][4], al2[2][4];
#pragma unroll
            for (int mt = 0; mt < 2; mt++) {
                int rb = m0 + mt * 16 + lr;
                ah[mt][0] = *(const unsigned*)(Ah + rb * 40 + kb + lc);
                ah[mt][1] = *(const unsigned*)(Ah + (rb + 8) * 40 + kb + lc);
                ah[mt][2] = *(const unsigned*)(Ah + rb * 40 + kb + lc + 8);
                ah[mt][3] = *(const unsigned*)(Ah + (rb + 8) * 40 + kb + lc + 8);
                al2[mt][0] = *(const unsigned*)(Al + rb * 40 + kb + lc);
                al2[mt][1] = *(const unsigned*)(Al + (rb + 8) * 40 + kb + lc);
                al2[mt][2] = *(const unsigned*)(Al + rb * 40 + kb + lc + 8);
                al2[mt][3] = *(const unsigned*)(Al + (rb + 8) * 40 + kb + lc + 8);
            }
#pragma unroll
            for (int nt = 0; nt < 8; nt++) {
                int nb = n0 + nt * 8 + lr;
                unsigned bh0 = *(const unsigned*)(Wh + nb * 40 + kb + lc);
                unsigned bh1 = *(const unsigned*)(Wh + nb * 40 + kb + lc + 8);
                unsigned bl0 = *(const unsigned*)(Wl + nb * 40 + kb + lc);
                unsigned bl1 = *(const unsigned*)(Wl + nb * 40 + kb + lc + 8);
#pragma unroll
                for (int mt = 0; mt < 2; mt++) {
                    mma_bf16(acc[mt][nt], ah[mt], bh0, bh1);
                    mma_bf16(acc[mt][nt], ah[mt], bl0, bl1);
                    mma_bf16(acc[mt][nt], al2[mt], bh0, bh1);
                }
            }
        }
    }

    // ---- epilogue: bias, store, stats ----
#pragma unroll
    for (int nt = 0; nt < 8; nt++) {
        int colg = ncolBase + n0 + nt * 8 + lc;
        float bz0 = bias ? __ldg(bias + colg) : 0.f;
        float bz1 = bias ? __ldg(bias + colg + 1) : 0.f;
        float s0 = 0.f, s1 = 0.f, q0 = 0.f, q1 = 0.f;
#pragma unroll
        for (int mt = 0; mt < 2; mt++) {
            int rg = rowBase + m0 + mt * 16 + lr;
            float c0 = acc[mt][nt][0] + bz0, c1 = acc[mt][nt][1] + bz1;
            float c2 = acc[mt][nt][2] + bz0, c3 = acc[mt][nt][3] + bz1;
            if (rg < rows) {
                *(float2*)(C + (size_t)rg * ldC + colg) = make_float2(c0, c1);
                if (STATS) { s0 += c0; s1 += c1; q0 += c0 * c0; q1 += c1 * c1; }
            }
            if (rg + 8 < rows) {
                *(float2*)(C + (size_t)(rg + 8) * ldC + colg) = make_float2(c2, c3);
                if (STATS) { s0 += c2; s1 += c3; q0 += c2 * c2; q1 += c3 * c3; }
            }
        }
        if (STATS) {
#pragma unroll
            for (int o = 4; o <= 16; o <<= 1) {
                s0 += __shfl_xor_sync(0xffffffffu, s0, o);
                s1 += __shfl_xor_sync(0xffffffffu, s1, o);
                q0 += __shfl_xor_sync(0xffffffffu, q0, o);
                q1 += __shfl_xor_sync(0xffffffffu, q1, o);
            }
            if (lr == 0) {
                atomicAdd(&sumOut[colg], (double)s0);
                atomicAdd(&sumOut[colg + 1], (double)s1);
                atomicAdd(&sumsqOut[colg], (double)q0);
                atomicAdd(&sumsqOut[colg + 1], (double)q1);
            }
        }
    }
}

// ---------------- edge stats: recompute X1 on the fly, accumulate BN1 stats ----------------
__global__ __launch_bounds__(256) void k_edgestats(
    const int* __restrict__ src, const int* __restrict__ dst,
    const float* __restrict__ pos,
    const float* __restrict__ wlast, const float* __restrict__ bm1,
    double* __restrict__ sum, double* __restrict__ sumsq)
{
    int lane = threadIdx.x & 31;
    int wg = (blockIdx.x * blockDim.x + threadIdx.x) >> 5;
    int nw = (gridDim.x * blockDim.x) >> 5;
    int c = lane * 4;
    float4 wl = *(const float4*)(wlast + c);
    float4 bb = *(const float4*)(bm1 + c);
    float4 s = make_float4(0.f, 0.f, 0.f, 0.f);
    float4 q = make_float4(0.f, 0.f, 0.f, 0.f);
    for (int e = wg; e < EE; e += nw) {
        int sj = src[e], dj = dst[e];
        float2 ps = ((const float2*)pos)[sj];
        float2 pd = ((const float2*)pos)[dj];
        float dx = ps.x - pd.x, dy = ps.y - pd.y;
        float dist = sqrtf(dx * dx + dy * dy);
        if (lane == 0) {
            ((float2*)g_diff)[e] = make_float2(dx, dy);
            g_dist[e] = dist;
            atomicAdd(&g_cnt[dj], 1.f);
        }
        float4 p = *(const float4*)(g_PQ + (size_t)dj * 256 + c);
        float4 qq = *(const float4*)(g_PQ + (size_t)sj * 256 + 128 + c);
        float4 x;
        x.x = p.x + qq.x + dist * wl.x + bb.x;
        x.y = p.y + qq.y + dist * wl.y + bb.y;
        x.z = p.z + qq.z + dist * wl.z + bb.z;
        x.w = p.w + qq.w + dist * wl.w + bb.w;
        s.x += x.x; s.y += x.y; s.z += x.z; s.w += x.w;
        q.x += x.x * x.x; q.y += x.y * x.y; q.z += x.z * x.z; q.w += x.w * x.w;
    }
    __shared__ float sb[8][128], qb[8][128];
    int wi = threadIdx.x >> 5;
    *(float4*)&sb[wi][c] = s;
    *(float4*)&qb[wi][c] = q;
    __syncthreads();
    if (threadIdx.x < 128) {
        float ts = 0.f, tq = 0.f;
#pragma unroll
        for (int i = 0; i < 8; i++) { ts += sb[i][threadIdx.x]; tq += qb[i][threadIdx.x]; }
        atomicAdd(&sum[threadIdx.x], (double)ts);
        atomicAdd(&sumsq[threadIdx.x], (double)tq);
    }
}

// ---------------- scalar stats ----------------
__global__ void k_stats1(const float* __restrict__ X, int n,
                         double* __restrict__ sum, double* __restrict__ sumsq)
{
    double s = 0.0, ss = 0.0;
    for (int i = blockIdx.x * blockDim.x + threadIdx.x; i < n; i += gridDim.x * blockDim.x) {
        float v = X[i];
        s += v;
        ss += (double)v * (double)v;
    }
    __shared__ double sb[256], ssb[256];
    sb[threadIdx.x] = s; ssb[threadIdx.x] = ss;
    __syncthreads();
    for (int o = 128; o > 0; o >>= 1) {
        if (threadIdx.x < o) {
            sb[threadIdx.x] += sb[threadIdx.x + o];
            ssb[threadIdx.x] += ssb[threadIdx.x + o];
        }
        __syncthreads();
    }
    if (threadIdx.x == 0) {
        atomicAdd(&sum[0], sb[0]);
        atomicAdd(&sumsq[0], ssb[0]);
    }
}

// ---------------- finalize BN affine ----------------
__global__ void k_fin(const double* __restrict__ sum, const double* __restrict__ sumsq,
                      const float* __restrict__ g, const float* __restrict__ bb,
                      float* __restrict__ acta, float* __restrict__ actc,
                      int rows, int ncols)
{
    int c = threadIdx.x;
    if (c < ncols) {
        double m = sum[c] / rows;
        double v = sumsq[c] / rows - m * m;
        float rstd = rsqrtf((float)v + BN_EPS);
        float a = g[c] * rstd;
        acta[c] = a;
        actc[c] = bb[c] - (float)m * a;
    }
}

// ---------------- gemv: sp[e] = bn_relu3(S[e]) . Wp2 + bp2 ----------------
__global__ void k_gemv(const float* __restrict__ S, const float* __restrict__ Wp2,
                       const float* __restrict__ bp2,
                       const float* __restrict__ acta, const float* __restrict__ actc,
                       float* __restrict__ out)
{
    int e = (blockIdx.x * blockDim.x + threadIdx.x) >> 5;
    int lane = threadIdx.x & 31;
    if (e >= EE) return;
    int c = lane * 4;
    float4 sv = *(const float4*)(S + (size_t)e * 128 + c);
    float4 wv = *(const float4*)(Wp2 + c);
    float d = fmaxf(fmaf(sv.x, acta[c + 0], actc[c + 0]), 0.f) * wv.x
            + fmaxf(fmaf(sv.y, acta[c + 1], actc[c + 1]), 0.f) * wv.y
            + fmaxf(fmaf(sv.z, acta[c + 2], actc[c + 2]), 0.f) * wv.z
            + fmaxf(fmaf(sv.w, acta[c + 3], actc[c + 3]), 0.f) * wv.w;
#pragma unroll
    for (int o = 16; o > 0; o >>= 1) d += __shfl_down_sync(0xffffffffu, d, o);
    if (lane == 0) out[e] = d + bp2[0];
}

// ---------------- pos aggregation ----------------
__global__ void k_posaggr(const int* __restrict__ dst,
                          const float* __restrict__ a4, const float* __restrict__ c4)
{
    int e = blockIdx.x * blockDim.x + threadIdx.x;
    if (e >= EE) return;
    float sc = fmaxf(fmaf(g_sp[e], a4[0], c4[0]), 0.f);
    float2 df = ((const float2*)g_diff)[e];
    int d = dst[e];
    red_add_v2(g_possum + 2 * (size_t)d, make_float2(df.x * sc, df.y * sc));
}

// ---------------- final residual write ----------------
__global__ void k_final(const float* __restrict__ h, const float* __restrict__ pos,
                        const float* __restrict__ a5, const float* __restrict__ c5,
                        float* __restrict__ out)
{
    int i = blockIdx.x * blockDim.x + threadIdx.x;
    if (i < NN * 128) {
        int c = i & 127;
        float u = g_U[i];
        out[i] = h[i] + fmaxf(fmaf(u, a5[c], c5[c]), 0.f);
    }
    if (i < NN) {
        float cnt = fmaxf(g_cnt[i], 1.f);
        out[NN * 128 + 2 * i + 0] = pos[2 * i + 0] + g_possum[2 * i + 0] / cnt;
        out[NN * 128 + 2 * i + 1] = pos[2 * i + 1] + g_possum[2 * i + 1] / cnt;
    }
}

extern "C" void kernel_launch(void* const* d_in, const int* in_sizes, int n_in,
                              void* d_out, int out_size)
{
    const float* h    = (const float*)d_in[0];
    const float* pos  = (const float*)d_in[1];
    const int*   ei   = (const int*)d_in[3];
    const int*   src  = ei;
    const int*   dst  = ei + EE;
    const float* Wm1  = (const float*)d_in[4];
    const float* bm1  = (const float*)d_in[5];
    const float* gm1  = (const float*)d_in[6];
    const float* bbm1 = (const float*)d_in[7];
    const float* Wm2  = (const float*)d_in[8];
    const float* bm2  = (const float*)d_in[9];
    const float* gm2  = (const float*)d_in[10];
    const float* bbm2 = (const float*)d_in[11];
    const float* Wp1  = (const float*)d_in[12];
    const float* bp1  = (const float*)d_in[13];
    const float* gp1  = (const float*)d_in[14];
    const float* bbp1 = (const float*)d_in[15];
    const float* Wp2  = (const float*)d_in[16];
    const float* bp2  = (const float*)d_in[17];
    const float* gp2  = (const float*)d_in[18];
    const float* bbp2 = (const float*)d_in[19];
    const float* Wu1  = (const float*)d_in[20];
    const float* bu1  = (const float*)d_in[21];
    const float* gu1  = (const float*)d_in[22];
    const float* bbu1 = (const float*)d_in[23];
    float* out = (float*)d_out;

    void* p;
    cudaGetSymbolAddress(&p, g_PQ);     float* PQ   = (float*)p;
    cudaGetSymbolAddress(&p, g_X2);     float* X2   = (float*)p;
    cudaGetSymbolAddress(&p, g_S);      float* S    = (float*)p;
    cudaGetSymbolAddress(&p, g_dist);   float* DIST = (float*)p;
    cudaGetSymbolAddress(&p, g_sp);     float* SP   = (float*)p;
    cudaGetSymbolAddress(&p, g_haggr);  float* HAGG = (float*)p;
    cudaGetSymbolAddress(&p, g_U);      float* U    = (float*)p;
    cudaGetSymbolAddress(&p, g_sum);    double* SUM = (double*)p;
    cudaGetSymbolAddress(&p, g_sumsq);  double* SSQ = (double*)p;
    cudaGetSymbolAddress(&p, g_acta);   float* ACTA = (float*)p;
    cudaGetSymbolAddress(&p, g_actc);   float* ACTC = (float*)p;
    cudaGetSymbolAddress(&p, g_wtpq_h); __nv_bfloat16* WPQh = (__nv_bfloat16*)p;
    cudaGetSymbolAddress(&p, g_wtpq_l); __nv_bfloat16* WPQl = (__nv_bfloat16*)p;
    cudaGetSymbolAddress(&p, g_wtm2_h); __nv_bfloat16* WM2h = (__nv_bfloat16*)p;
    cudaGetSymbolAddress(&p, g_wtm2_l); __nv_bfloat16* WM2l = (__nv_bfloat16*)p;
    cudaGetSymbolAddress(&p, g_wtp1_h); __nv_bfloat16* WP1h = (__nv_bfloat16*)p;
    cudaGetSymbolAddress(&p, g_wtp1_l); __nv_bfloat16* WP1l = (__nv_bfloat16*)p;
    cudaGetSymbolAddress(&p, g_wtu_h);  __nv_bfloat16* WUh  = (__nv_bfloat16*)p;
    cudaGetSymbolAddress(&p, g_wtu_l);  __nv_bfloat16* WUl  = (__nv_bfloat16*)p;

    const float* wlast = Wm1 + 256 * 128;
    const int ET = (EE + 127) / 128;   // 3907 row tiles for edges
    const int NT = (NN + 127) / 128;   // 391 row tiles for nodes

    k_zero<<<2048, 256>>>();
    k_prepw<<<256, 256>>>(Wm1, Wm2, Wp1, Wu1);

    // PQ = h @ [Wm1_top | Wm1_mid]  (N=256 output)
    k_gemm_tc<0, false, false, false><<<dim3(NT, 2), 256>>>(
        h, nullptr, WPQh, WPQl, nullptr, nullptr, nullptr,
        PQ, NN, 128, 256, nullptr, nullptr, nullptr, nullptr, nullptr,
        nullptr, nullptr, nullptr);

    // BN1 stats (recompute X1 on the fly) + diff/dist/cnt
    k_edgestats<<<592, 256>>>(src, dst, pos, wlast, bm1, SUM + 0, SSQ + 0);
    k_fin<<<1, 128>>>(SUM + 0, SSQ + 0, gm1, bbm1, ACTA + 0, ACTC + 0, EE, 128);

    // GEMM2: X2 = bn_relu1(assemble(X1)) @ Wm2 + bm2, fused BN2 stats
    k_gemm_tc<2, true, true, false><<<dim3(ET, 1), 256>>>(
        nullptr, nullptr, WM2h, WM2l, bm2, ACTA + 0, ACTC + 0,
        X2, EE, 128, 128, src, dst, DIST, wlast, bm1,
        SUM + 128, SSQ + 128, nullptr);
    k_fin<<<1, 128>>>(SUM + 128, SSQ + 128, gm2, bbm2, ACTA + 128, ACTC + 128, EE, 128);

    // GEMM3: S = bn_relu2(X2) @ Wp1 + bp1, fused BN3 stats + h-aggregation
    k_gemm_tc<0, true, true, true><<<dim3(ET, 1), 256>>>(
        X2, nullptr, WP1h, WP1l, bp1, ACTA + 128, ACTC + 128,
        S, EE, 128, 128, nullptr, dst, nullptr, nullptr, nullptr,
        SUM + 256, SSQ + 256, HAGG);
    k_fin<<<1, 128>>>(SUM + 256, SSQ + 256, gp1, bbp1, ACTA + 256, ACTC + 256, EE, 128);

    // pos layer 2 (gemv) + BN4 stats
    k_gemv<<<EE / 8, 256>>>(S, Wp2, bp2, ACTA + 256, ACTC + 256, SP);
    k_stats1<<<1024, 256>>>(SP, EE, SUM + 384, SSQ + 384);
    k_fin<<<1, 128>>>(SUM + 384, SSQ + 384, gp2, bbp2, ACTA + 384, ACTC + 384, EE, 1);

    // pos aggregation
    k_posaggr<<<(EE + 255) / 256, 256>>>(dst, ACTA + 384, ACTC + 384);

    // update MLP: U = [h | h_aggr] @ Wu1 + bu1, fused BN5 stats
    k_gemm_tc<1, false, true, false><<<dim3(NT, 1), 256>>>(
        h, HAGG, WUh, WUl, bu1, nullptr, nullptr,
        U, NN, 256, 128, nullptr, nullptr, nullptr, nullptr, nullptr,
        SUM + 512, SSQ + 512, nullptr);
    k_fin<<<1, 128>>>(SUM + 512, SSQ + 512, gu1, bbu1, ACTA + 512, ACTC + 512, NN, 128);

    // residual outputs
    k_final<<<(NN * 128 + 255) / 256, 256>>>(h, pos, ACTA + 512, ACTC + 512, out);
}

// round 4
// speedup vs baseline: 3.0611x; 1.6088x over previous
#include <cuda_runtime.h>
#include <cuda_bf16.h>
#include <math.h>
#include <stdint.h>

#define NN 50000
#define EE 500000
#define BN_EPS 1e-5f

// ---------------- global scratch ----------------
__device__ float g_PQ[NN * 256];               // [n][0:128]=P(dst), [128:256]=Q(src)
__device__ float g_X2[(size_t)EE * 128];
__device__ __nv_bfloat16 g_S[(size_t)EE * 128];
__device__ float g_diff[EE * 2];
__device__ float g_dist[EE];
__device__ float g_sp[EE];
__device__ float g_haggr[NN * 128];
__device__ float g_possum[NN * 2];
__device__ float g_cnt[NN];
__device__ float g_U[NN * 128];
__device__ double g_sum[5 * 128];
__device__ double g_sumsq[5 * 128];
__device__ float g_acta[5 * 128];
__device__ float g_actc[5 * 128];
// prestaged weights, smem-image layout:
// chunk c (32 k-cols): [plane(2)][n(128)][40] bf16, 10240 bf16 per chunk; cols 32..39 = 0
__device__ __nv_bfloat16 g_wpq[2 * 4 * 10240];   // 2 n-tiles x 4 chunks
__device__ __nv_bfloat16 g_wm2[4 * 10240];
__device__ __nv_bfloat16 g_wp1[4 * 10240];
__device__ __nv_bfloat16 g_wu[8 * 10240];

// ---------------- helpers ----------------
__device__ __forceinline__ void red_add_v4(float* p, float4 v) {
    asm volatile("red.global.add.v4.f32 [%0], {%1,%2,%3,%4};"
                 :: "l"(p), "f"(v.x), "f"(v.y), "f"(v.z), "f"(v.w) : "memory");
}
__device__ __forceinline__ void red_add_v2(float* p, float2 v) {
    asm volatile("red.global.add.v2.f32 [%0], {%1,%2};"
                 :: "l"(p), "f"(v.x), "f"(v.y) : "memory");
}
__device__ __forceinline__ void red_add_f64(double* p, double v) {
    asm volatile("red.global.add.f64 [%0], %1;" :: "l"(p), "d"(v) : "memory");
}
__device__ __forceinline__ unsigned pkbf(__nv_bfloat16 a, __nv_bfloat16 b) {
    return ((unsigned)__bfloat16_as_ushort(b) << 16) | (unsigned)__bfloat16_as_ushort(a);
}
__device__ __forceinline__ void split1(float x, __nv_bfloat16& h, __nv_bfloat16& l) {
    h = __float2bfloat16(x);
    l = __float2bfloat16(x - __bfloat162float(h));
}
__device__ __forceinline__ void mma_bf16(float* d, const unsigned* a, unsigned b0, unsigned b1) {
    asm volatile("mma.sync.aligned.m16n8k16.row.col.f32.bf16.bf16.f32 "
                 "{%0,%1,%2,%3},{%4,%5,%6,%7},{%8,%9},{%0,%1,%2,%3};"
                 : "+f"(d[0]), "+f"(d[1]), "+f"(d[2]), "+f"(d[3])
                 : "r"(a[0]), "r"(a[1]), "r"(a[2]), "r"(a[3]), "r"(b0), "r"(b1));
}

#define CHUNK_BF16 10240            // one 32-k chunk, both planes
#define PLANE_BF16 5120             // 128 x 40
#define STAGE_F32  (128 * 132)      // epilogue staging
#define OFF_RED    (STAGE_F32 * 4)  // bytes; partial-sum region after stage

// ---------------- zero scratch ----------------
__global__ void k_zero() {
    int idx = blockIdx.x * blockDim.x + threadIdx.x;
    int stride = gridDim.x * blockDim.x;
    for (int i = idx; i < NN * 128; i += stride) g_haggr[i] = 0.f;
    for (int i = idx; i < NN * 2; i += stride) g_possum[i] = 0.f;
    for (int i = idx; i < NN; i += stride) g_cnt[i] = 0.f;
    if (idx < 5 * 128) { g_sum[idx] = 0.0; g_sumsq[idx] = 0.0; }
}

// ---------------- weight prep into smem-image layout ----------------
__device__ __forceinline__ void prep_store(__nv_bfloat16* dstArr, int i, float v) {
    // i indexes [chunk][plane][n][40]
    int ci = i / CHUNK_BF16;
    int rem = i - ci * CHUNK_BF16;
    int plane = rem / PLANE_BF16;
    (void)plane;
    dstArr[i] = __float2bfloat16(v);
}
__global__ void k_prepw(const float* __restrict__ Wm1, const float* __restrict__ Wm2,
                        const float* __restrict__ Wp1, const float* __restrict__ Wu1)
{
    int idx = blockIdx.x * blockDim.x + threadIdx.x;
    int stride = gridDim.x * blockDim.x;
    // PQ: chunkIdx = nt*4 + kc
    for (int i = idx; i < 2 * 4 * CHUNK_BF16; i += stride) {
        int ci = i / CHUNK_BF16, rem = i % CHUNK_BF16;
        int plane = rem / PLANE_BF16, r2 = rem % PLANE_BF16;
        int n = r2 / 40, k = r2 % 40;
        int nt = ci >> 2, kc = ci & 3, kg = kc * 32 + k;
        float v = 0.f;
        if (k < 32) v = nt ? Wm1[(128 + kg) * 128 + n] : Wm1[kg * 128 + n];
        __nv_bfloat16 h, l; split1(v, h, l);
        g_wpq[i] = plane ? l : h;
    }
    // M2, P1: chunkIdx = kc
    for (int i = idx; i < 4 * CHUNK_BF16; i += stride) {
        int ci = i / CHUNK_BF16, rem = i % CHUNK_BF16;
        int plane = rem / PLANE_BF16, r2 = rem % PLANE_BF16;
        int n = r2 / 40, k = r2 % 40;
        int kg = ci * 32 + k;
        float v2 = (k < 32) ? Wm2[kg * 128 + n] : 0.f;
        float vp = (k < 32) ? Wp1[kg * 128 + n] : 0.f;
        __nv_bfloat16 h, l;
        split1(v2, h, l); g_wm2[i] = plane ? l : h;
        split1(vp, h, l); g_wp1[i] = plane ? l : h;
    }
    // U: chunkIdx = kc (K=256)
    for (int i = idx; i < 8 * CHUNK_BF16; i += stride) {
        int ci = i / CHUNK_BF16, rem = i % CHUNK_BF16;
        int plane = rem / PLANE_BF16, r2 = rem % PLANE_BF16;
        int n = r2 / 40, k = r2 % 40;
        int kg = ci * 32 + k;
        float v = (k < 32) ? Wu1[kg * 128 + n] : 0.f;
        __nv_bfloat16 h, l; split1(v, h, l);
        g_wu[i] = plane ? l : h;
    }
}

// ---------------- pipelined mma.sync GEMM ----------------
// C[rows, ·] = act(A[rows, KC*32]) @ W + bias
// AMODE: 0 plain A(128); 1 concat [A|A2] (KC=8); 2 edge-assembled from g_PQ
template<int AMODE, bool BN, bool STATS, bool AGGR, bool OUTBF16, int KC>
__global__ __launch_bounds__(512) void k_gemm(
    const float* __restrict__ A, const float* __restrict__ A2,
    const __nv_bfloat16* __restrict__ Wt,
    const float* __restrict__ bias,
    const float* __restrict__ acta, const float* __restrict__ actc,
    float* __restrict__ Cf, __nv_bfloat16* __restrict__ Cb,
    int rows, int ldC,
    const int* __restrict__ srcIdx, const int* __restrict__ dstIdx,
    const float* __restrict__ dist,
    const float* __restrict__ wlast, const float* __restrict__ bm1v,
    double* __restrict__ sumOut, double* __restrict__ sumsqOut,
    float* __restrict__ aggrOut)
{
    extern __shared__ char smem[];
    __nv_bfloat16* smW = (__nv_bfloat16*)smem;
    __nv_bfloat16* smA = smW + KC * CHUNK_BF16;

    const int t = threadIdx.x;
    const int w = t >> 5, l = t & 31;
    const int wm = w & 3, wn = w >> 2;      // warp tile: m 32 rows, n 32 cols
    const int lr = l >> 2, lc = 2 * (l & 3);
    const int rowBase = blockIdx.x * 128;
    const int ncolBase = blockIdx.y * 128;

    // ---- whole-K W copy into smem ----
    {
        const uint4* s4 = (const uint4*)(Wt + (size_t)blockIdx.y * KC * CHUNK_BF16);
        uint4* d4 = (uint4*)smW;
        const int tot = KC * CHUNK_BF16 * 2 / 16;
#pragma unroll 4
        for (int i = t; i < tot; i += 512) d4[i] = s4[i];
    }

    // A-fill mapping: 4 threads per row, 8 k-cols each
    const int rl = t >> 2;
    const int cg = (t & 3) * 8;
    const int grow = rowBase + rl;
    const bool avalid = grow < rows;
    int ed = 0, es = 0;
    float de = 0.f;
    if ((AMODE == 2 || AGGR) && avalid) ed = dstIdx[grow];
    if (AMODE == 2 && avalid) { es = srcIdx[grow]; de = dist[grow]; }

    float acc[2][4][4];
#pragma unroll
    for (int i = 0; i < 2; i++)
#pragma unroll
        for (int j = 0; j < 4; j++)
#pragma unroll
            for (int k = 0; k < 4; k++) acc[i][j][k] = 0.f;

    float4 pv0, pv1, pv2, pv3;

    auto loadA = [&](int kc) {
        int kg = kc * 32 + cg;
        if (avalid) {
            if (AMODE == 0) {
                pv0 = *(const float4*)(A + (size_t)grow * 128 + kg);
                pv1 = *(const float4*)(A + (size_t)grow * 128 + kg + 4);
            } else if (AMODE == 1) {
                const float* As = (kg < 128) ? A : A2;
                int k2 = kg & 127;
                pv0 = *(const float4*)(As + (size_t)grow * 128 + k2);
                pv1 = *(const float4*)(As + (size_t)grow * 128 + k2 + 4);
            } else {
                pv0 = *(const float4*)(g_PQ + (size_t)ed * 256 + kg);
                pv1 = *(const float4*)(g_PQ + (size_t)ed * 256 + kg + 4);
                pv2 = *(const float4*)(g_PQ + (size_t)es * 256 + 128 + kg);
                pv3 = *(const float4*)(g_PQ + (size_t)es * 256 + 128 + kg + 4);
            }
        }
    };

    auto storeA = [&](int kc, int st) {
        int kg = kc * 32 + cg;
        float vv[8] = {0.f, 0.f, 0.f, 0.f, 0.f, 0.f, 0.f, 0.f};
        if (avalid) {
            vv[0] = pv0.x; vv[1] = pv0.y; vv[2] = pv0.z; vv[3] = pv0.w;
            vv[4] = pv1.x; vv[5] = pv1.y; vv[6] = pv1.z; vv[7] = pv1.w;
            if (AMODE == 2) {
                float q4[8] = {pv2.x, pv2.y, pv2.z, pv2.w, pv3.x, pv3.y, pv3.z, pv3.w};
#pragma unroll
                for (int j = 0; j < 8; j++) {
                    float wl = __ldg(wlast + kg + j);
                    float bb = __ldg(bm1v + kg + j);
                    vv[j] = vv[j] + q4[j] + de * wl + bb;
                }
            }
            if (BN) {
#pragma unroll
                for (int j = 0; j < 8; j++)
                    vv[j] = fmaxf(fmaf(vv[j], __ldg(acta + kg + j), __ldg(actc + kg + j)), 0.f);
            }
            if (AGGR) {
                red_add_v4(aggrOut + (size_t)ed * 128 + kg,
                           make_float4(vv[0], vv[1], vv[2], vv[3]));
                red_add_v4(aggrOut + (size_t)ed * 128 + kg + 4,
                           make_float4(vv[4], vv[5], vv[6], vv[7]));
            }
        }
        unsigned ph[4], pl[4];
#pragma unroll
        for (int j = 0; j < 4; j++) {
            __nv_bfloat16 h0, l0, h1, l1;
            split1(vv[2 * j], h0, l0);
            split1(vv[2 * j + 1], h1, l1);
            ph[j] = pkbf(h0, h1);
            pl[j] = pkbf(l0, l1);
        }
        __nv_bfloat16* Ah = smA + st * CHUNK_BF16;
        *(uint4*)(Ah + rl * 40 + cg) = make_uint4(ph[0], ph[1], ph[2], ph[3]);
        *(uint4*)(Ah + PLANE_BF16 + rl * 40 + cg) = make_uint4(pl[0], pl[1], pl[2], pl[3]);
    };

    loadA(0);
    storeA(0, 0);
    __syncthreads();   // W + A0 ready

    for (int kc = 0; kc < KC; kc++) {
        if (kc + 1 < KC) loadA(kc + 1);
        const __nv_bfloat16* Ah = smA + (kc & 1) * CHUNK_BF16;
        const __nv_bfloat16* Al = Ah + PLANE_BF16;
        const __nv_bfloat16* Bh = smW + kc * CHUNK_BF16;
        const __nv_bfloat16* Bl = Bh + PLANE_BF16;
#pragma unroll
        for (int ks = 0; ks < 2; ks++) {
            int kb = ks * 16;
            unsigned ah[2][4], al2[2][4];
#pragma unroll
            for (int mt = 0; mt < 2; mt++) {
                int rb = wm * 32 + mt * 16 + lr;
                ah[mt][0] = *(const unsigned*)(Ah + rb * 40 + kb + lc);
                ah[mt][1] = *(const unsigned*)(Ah + (rb + 8) * 40 + kb + lc);
                ah[mt][2] = *(const unsigned*)(Ah + rb * 40 + kb + lc + 8);
                ah[mt][3] = *(const unsigned*)(Ah + (rb + 8) * 40 + kb + lc + 8);
                al2[mt][0] = *(const unsigned*)(Al + rb * 40 + kb + lc);
                al2[mt][1] = *(const unsigned*)(Al + (rb + 8) * 40 + kb + lc);
                al2[mt][2] = *(const unsigned*)(Al + rb * 40 + kb + lc + 8);
                al2[mt][3] = *(const unsigned*)(Al + (rb + 8) * 40 + kb + lc + 8);
            }
#pragma unroll
            for (int nt = 0; nt < 4; nt++) {
                int nb = wn * 32 + nt * 8 + lr;
                unsigned bh0 = *(const unsigned*)(Bh + nb * 40 + kb + lc);
                unsigned bh1 = *(const unsigned*)(Bh + nb * 40 + kb + lc + 8);
                unsigned bl0 = *(const unsigned*)(Bl + nb * 40 + kb + lc);
                unsigned bl1 = *(const unsigned*)(Bl + nb * 40 + kb + lc + 8);
#pragma unroll
                for (int mt = 0; mt < 2; mt++) {
                    mma_bf16(acc[mt][nt], ah[mt], bh0, bh1);
                    mma_bf16(acc[mt][nt], ah[mt], bl0, bl1);
                    mma_bf16(acc[mt][nt], al2[mt], bh0, bh1);
                }
            }
        }
        if (kc + 1 < KC) {
            __syncthreads();           // all warps done with A buf (kc+1)&1
            storeA(kc + 1, (kc + 1) & 1);
            __syncthreads();           // fill visible
        }
    }
    __syncthreads();   // before stage reuse of smem

    // ---- epilogue: acc -> stage (bias, zero invalid rows) ----
    float* stage = (float*)smem;
#pragma unroll
    for (int mt = 0; mt < 2; mt++) {
#pragma unroll
        for (int nt = 0; nt < 4; nt++) {
            int row = wm * 32 + mt * 16 + lr;
            int col = wn * 32 + nt * 8 + lc;
            float b0 = bias ? __ldg(bias + ncolBase + col) : 0.f;
            float b1 = bias ? __ldg(bias + ncolBase + col + 1) : 0.f;
            bool v0 = (rowBase + row) < rows;
            bool v1 = (rowBase + row + 8) < rows;
            stage[row * 132 + col]       = v0 ? acc[mt][nt][0] + b0 : 0.f;
            stage[row * 132 + col + 1]   = v0 ? acc[mt][nt][1] + b1 : 0.f;
            stage[(row + 8) * 132 + col]     = v1 ? acc[mt][nt][2] + b0 : 0.f;
            stage[(row + 8) * 132 + col + 1] = v1 ? acc[mt][nt][3] + b1 : 0.f;
        }
    }
    __syncthreads();

    // stats partials
    float* sb = (float*)(smem + OFF_RED);
    float* qb = sb + 512;
    if (STATS) {
        int c = t & 127, qq = t >> 7;
        float s = 0.f, q = 0.f;
#pragma unroll 8
        for (int r = 0; r < 32; r++) {
            float v = stage[(qq * 32 + r) * 132 + c];
            s += v; q += v * v;
        }
        sb[qq * 128 + c] = s;
        qb[qq * 128 + c] = q;
    }

    // coalesced output store
    for (int i = t; i < 128 * 32; i += 512) {
        int row = i >> 5;
        int colq = (i & 31) * 4;
        int rowg = rowBase + row;
        if (rowg < rows) {
            float4 v = *(float4*)(stage + row * 132 + colq);
            if (!OUTBF16) {
                *(float4*)(Cf + (size_t)rowg * ldC + ncolBase + colq) = v;
            } else {
                uint2 o = make_uint2(pkbf(__float2bfloat16(v.x), __float2bfloat16(v.y)),
                                     pkbf(__float2bfloat16(v.z), __float2bfloat16(v.w)));
                *(uint2*)(Cb + (size_t)rowg * 128 + colq) = o;
            }
        }
    }

    if (STATS) {
        __syncthreads();
        if (t < 128) {
            float s = sb[t] + sb[128 + t] + sb[256 + t] + sb[384 + t];
            float q = qb[t] + qb[128 + t] + qb[256 + t] + qb[384 + t];
            red_add_f64(&sumOut[ncolBase + t], (double)s);
            red_add_f64(&sumsqOut[ncolBase + t], (double)q);
        }
    }
}

// ---------------- edge stats (BN1) + diff/dist/cnt ----------------
__global__ __launch_bounds__(256) void k_edgestats(
    const int* __restrict__ src, const int* __restrict__ dst,
    const float* __restrict__ pos,
    const float* __restrict__ wlast, const float* __restrict__ bm1,
    double* __restrict__ sum, double* __restrict__ sumsq)
{
    int lane = threadIdx.x & 31;
    int wg = (blockIdx.x * blockDim.x + threadIdx.x) >> 5;
    int nw = (gridDim.x * blockDim.x) >> 5;
    int c = lane * 4;
    float4 wl = *(const float4*)(wlast + c);
    float4 bb = *(const float4*)(bm1 + c);
    float4 s = make_float4(0.f, 0.f, 0.f, 0.f);
    float4 q = make_float4(0.f, 0.f, 0.f, 0.f);
    for (int e = wg; e < EE; e += nw) {
        int sj = src[e], dj = dst[e];
        float2 ps = ((const float2*)pos)[sj];
        float2 pd = ((const float2*)pos)[dj];
        float dx = ps.x - pd.x, dy = ps.y - pd.y;
        float dist = sqrtf(dx * dx + dy * dy);
        if (lane == 0) {
            ((float2*)g_diff)[e] = make_float2(dx, dy);
            g_dist[e] = dist;
            atomicAdd(&g_cnt[dj], 1.f);
        }
        float4 p = *(const float4*)(g_PQ + (size_t)dj * 256 + c);
        float4 qq = *(const float4*)(g_PQ + (size_t)sj * 256 + 128 + c);
        float4 x;
        x.x = p.x + qq.x + dist * wl.x + bb.x;
        x.y = p.y + qq.y + dist * wl.y + bb.y;
        x.z = p.z + qq.z + dist * wl.z + bb.z;
        x.w = p.w + qq.w + dist * wl.w + bb.w;
        s.x += x.x; s.y += x.y; s.z += x.z; s.w += x.w;
        q.x += x.x * x.x; q.y += x.y * x.y; q.z += x.z * x.z; q.w += x.w * x.w;
    }
    __shared__ float sb[8][128], qb[8][128];
    int wi = threadIdx.x >> 5;
    *(float4*)&sb[wi][c] = s;
    *(float4*)&qb[wi][c] = q;
    __syncthreads();
    if (threadIdx.x < 128) {
        float ts = 0.f, tq = 0.f;
#pragma unroll
        for (int i = 0; i < 8; i++) { ts += sb[i][threadIdx.x]; tq += qb[i][threadIdx.x]; }
        red_add_f64(&sum[threadIdx.x], (double)ts);
        red_add_f64(&sumsq[threadIdx.x], (double)tq);
    }
}

// ---------------- scalar stats ----------------
__global__ void k_stats1(const float* __restrict__ X, int n,
                         double* __restrict__ sum, double* __restrict__ sumsq)
{
    double s = 0.0, ss = 0.0;
    for (int i = blockIdx.x * blockDim.x + threadIdx.x; i < n; i += gridDim.x * blockDim.x) {
        float v = X[i];
        s += v;
        ss += (double)v * (double)v;
    }
    __shared__ double sb[256], ssb[256];
    sb[threadIdx.x] = s; ssb[threadIdx.x] = ss;
    __syncthreads();
    for (int o = 128; o > 0; o >>= 1) {
        if (threadIdx.x < o) {
            sb[threadIdx.x] += sb[threadIdx.x + o];
            ssb[threadIdx.x] += ssb[threadIdx.x + o];
        }
        __syncthreads();
    }
    if (threadIdx.x == 0) {
        red_add_f64(&sum[0], sb[0]);
        red_add_f64(&sumsq[0], ssb[0]);
    }
}

// ---------------- finalize BN affine ----------------
__global__ void k_fin(const double* __restrict__ sum, const double* __restrict__ sumsq,
                      const float* __restrict__ g, const float* __restrict__ bb,
                      float* __restrict__ acta, float* __restrict__ actc,
                      int rows, int ncols)
{
    int c = threadIdx.x;
    if (c < ncols) {
        double m = sum[c] / rows;
        double v = sumsq[c] / rows - m * m;
        float rstd = rsqrtf((float)v + BN_EPS);
        float a = g[c] * rstd;
        acta[c] = a;
        actc[c] = bb[c] - (float)m * a;
    }
}

// ---------------- gemv over bf16 S ----------------
__global__ void k_gemv(const __nv_bfloat16* __restrict__ S, const float* __restrict__ Wp2,
                       const float* __restrict__ bp2,
                       const float* __restrict__ acta, const float* __restrict__ actc,
                       float* __restrict__ out)
{
    int e = (blockIdx.x * blockDim.x + threadIdx.x) >> 5;
    int lane = threadIdx.x & 31;
    if (e >= EE) return;
    int c = lane * 4;
    uint2 raw = *(const uint2*)(S + (size_t)e * 128 + c);
    float v0 = __bfloat162float(__ushort_as_bfloat16((unsigned short)(raw.x & 0xffff)));
    float v1 = __bfloat162float(__ushort_as_bfloat16((unsigned short)(raw.x >> 16)));
    float v2 = __bfloat162float(__ushort_as_bfloat16((unsigned short)(raw.y & 0xffff)));
    float v3 = __bfloat162float(__ushort_as_bfloat16((unsigned short)(raw.y >> 16)));
    float4 wv = *(const float4*)(Wp2 + c);
    float d = fmaxf(fmaf(v0, acta[c + 0], actc[c + 0]), 0.f) * wv.x
            + fmaxf(fmaf(v1, acta[c + 1], actc[c + 1]), 0.f) * wv.y
            + fmaxf(fmaf(v2, acta[c + 2], actc[c + 2]), 0.f) * wv.z
            + fmaxf(fmaf(v3, acta[c + 3], actc[c + 3]), 0.f) * wv.w;
#pragma unroll
    for (int o = 16; o > 0; o >>= 1) d += __shfl_down_sync(0xffffffffu, d, o);
    if (lane == 0) out[e] = d + bp2[0];
}

// ---------------- pos aggregation ----------------
__global__ void k_posaggr(const int* __restrict__ dst,
                          const float* __restrict__ a4, const float* __restrict__ c4)
{
    int e = blockIdx.x * blockDim.x + threadIdx.x;
    if (e >= EE) return;
    float sc = fmaxf(fmaf(g_sp[e], a4[0], c4[0]), 0.f);
    float2 df = ((const float2*)g_diff)[e];
    int d = dst[e];
    red_add_v2(g_possum + 2 * (size_t)d, make_float2(df.x * sc, df.y * sc));
}

// ---------------- final residual write ----------------
__global__ void k_final(const float* __restrict__ h, const float* __restrict__ pos,
                        const float* __restrict__ a5, const float* __restrict__ c5,
                        float* __restrict__ out)
{
    int i = blockIdx.x * blockDim.x + threadIdx.x;
    if (i < NN * 128) {
        int c = i & 127;
        float u = g_U[i];
        out[i] = h[i] + fmaxf(fmaf(u, a5[c], c5[c]), 0.f);
    }
    if (i < NN) {
        float cnt = fmaxf(g_cnt[i], 1.f);
        out[NN * 128 + 2 * i + 0] = pos[2 * i + 0] + g_possum[2 * i + 0] / cnt;
        out[NN * 128 + 2 * i + 1] = pos[2 * i + 1] + g_possum[2 * i + 1] / cnt;
    }
}

extern "C" void kernel_launch(void* const* d_in, const int* in_sizes, int n_in,
                              void* d_out, int out_size)
{
    const float* h    = (const float*)d_in[0];
    const float* pos  = (const float*)d_in[1];
    const int*   ei   = (const int*)d_in[3];
    const int*   src  = ei;
    const int*   dst  = ei + EE;
    const float* Wm1  = (const float*)d_in[4];
    const float* bm1  = (const float*)d_in[5];
    const float* gm1  = (const float*)d_in[6];
    const float* bbm1 = (const float*)d_in[7];
    const float* Wm2  = (const float*)d_in[8];
    const float* bm2  = (const float*)d_in[9];
    const float* gm2  = (const float*)d_in[10];
    const float* bbm2 = (const float*)d_in[11];
    const float* Wp1  = (const float*)d_in[12];
    const float* bp1  = (const float*)d_in[13];
    const float* gp1  = (const float*)d_in[14];
    const float* bbp1 = (const float*)d_in[15];
    const float* Wp2  = (const float*)d_in[16];
    const float* bp2  = (const float*)d_in[17];
    const float* gp2  = (const float*)d_in[18];
    const float* bbp2 = (const float*)d_in[19];
    const float* Wu1  = (const float*)d_in[20];
    const float* bu1  = (const float*)d_in[21];
    const float* gu1  = (const float*)d_in[22];
    const float* bbu1 = (const float*)d_in[23];
    float* out = (float*)d_out;

    void* p;
    cudaGetSymbolAddress(&p, g_PQ);   float* PQ   = (float*)p;
    cudaGetSymbolAddress(&p, g_X2);   float* X2   = (float*)p;
    cudaGetSymbolAddress(&p, g_S);    __nv_bfloat16* S = (__nv_bfloat16*)p;
    cudaGetSymbolAddress(&p, g_dist); float* DIST = (float*)p;
    cudaGetSymbolAddress(&p, g_sp);   float* SP   = (float*)p;
    cudaGetSymbolAddress(&p, g_haggr); float* HAGG = (float*)p;
    cudaGetSymbolAddress(&p, g_U);    float* U    = (float*)p;
    cudaGetSymbolAddress(&p, g_sum);  double* SUM = (double*)p;
    cudaGetSymbolAddress(&p, g_sumsq); double* SSQ = (double*)p;
    cudaGetSymbolAddress(&p, g_acta); float* ACTA = (float*)p;
    cudaGetSymbolAddress(&p, g_actc); float* ACTC = (float*)p;
    cudaGetSymbolAddress(&p, g_wpq);  __nv_bfloat16* WPQ = (__nv_bfloat16*)p;
    cudaGetSymbolAddress(&p, g_wm2);  __nv_bfloat16* WM2 = (__nv_bfloat16*)p;
    cudaGetSymbolAddress(&p, g_wp1);  __nv_bfloat16* WP1 = (__nv_bfloat16*)p;
    cudaGetSymbolAddress(&p, g_wu);   __nv_bfloat16* WU  = (__nv_bfloat16*)p;

    const float* wlast = Wm1 + 256 * 128;
    const int ET = (EE + 127) / 128;   // 3907
    const int NT = (NN + 127) / 128;   // 391
    const int SM4 = 4 * 20480 + 40960; // 122880 (KC=4)
    const int SM8 = 8 * 20480 + 40960; // 204800 (KC=8)

    cudaFuncSetAttribute((const void*)k_gemm<0, false, false, false, false, 4>,
                         cudaFuncAttributeMaxDynamicSharedMemorySize, SM4);
    cudaFuncSetAttribute((const void*)k_gemm<2, true, true, false, false, 4>,
                         cudaFuncAttributeMaxDynamicSharedMemorySize, SM4);
    cudaFuncSetAttribute((const void*)k_gemm<0, true, true, true, true, 4>,
                         cudaFuncAttributeMaxDynamicSharedMemorySize, SM4);
    cudaFuncSetAttribute((const void*)k_gemm<1, false, true, false, false, 8>,
                         cudaFuncAttributeMaxDynamicSharedMemorySize, SM8);

    k_zero<<<2048, 256>>>();
    k_prepw<<<256, 256>>>(Wm1, Wm2, Wp1, Wu1);

    // PQ = h @ [Wm1_top | Wm1_mid]  (2 column tiles)
    k_gemm<0, false, false, false, false, 4><<<dim3(NT, 2), 512, SM4>>>(
        h, nullptr, WPQ, nullptr, nullptr, nullptr,
        PQ, nullptr, NN, 256, nullptr, nullptr, nullptr, nullptr, nullptr,
        nullptr, nullptr, nullptr);

    // BN1 stats (recompute X1 on the fly) + diff/dist/cnt
    k_edgestats<<<1184, 256>>>(src, dst, pos, wlast, bm1, SUM + 0, SSQ + 0);
    k_fin<<<1, 128>>>(SUM + 0, SSQ + 0, gm1, bbm1, ACTA + 0, ACTC + 0, EE, 128);

    // GEMM2: X2 = bn_relu1(assemble(X1)) @ Wm2 + bm2, fused BN2 stats
    k_gemm<2, true, true, false, false, 4><<<dim3(ET, 1), 512, SM4>>>(
        nullptr, nullptr, WM2, bm2, ACTA + 0, ACTC + 0,
        X2, nullptr, EE, 128, src, dst, DIST, wlast, bm1,
        SUM + 128, SSQ + 128, nullptr);
    k_fin<<<1, 128>>>(SUM + 128, SSQ + 128, gm2, bbm2, ACTA + 128, ACTC + 128, EE, 128);

    // GEMM3: S = bn_relu2(X2) @ Wp1 + bp1 (bf16 out), fused BN3 stats + h-aggr
    k_gemm<0, true, true, true, true, 4><<<dim3(ET, 1), 512, SM4>>>(
        X2, nullptr, WP1, bp1, ACTA + 128, ACTC + 128,
        nullptr, S, EE, 128, nullptr, dst, nullptr, nullptr, nullptr,
        SUM + 256, SSQ + 256, HAGG);
    k_fin<<<1, 128>>>(SUM + 256, SSQ + 256, gp1, bbp1, ACTA + 256, ACTC + 256, EE, 128);

    // pos layer 2 (gemv) + BN4 stats
    k_gemv<<<EE / 8, 256>>>(S, Wp2, bp2, ACTA + 256, ACTC + 256, SP);
    k_stats1<<<1024, 256>>>(SP, EE, SUM + 384, SSQ + 384);
    k_fin<<<1, 128>>>(SUM + 384, SSQ + 384, gp2, bbp2, ACTA + 384, ACTC + 384, EE, 1);

    // pos aggregation
    k_posaggr<<<(EE + 255) / 256, 256>>>(dst, ACTA + 384, ACTC + 384);

    // update MLP: U = [h | h_aggr] @ Wu1 + bu1, fused BN5 stats
    k_gemm<1, false, true, false, false, 8><<<dim3(NT, 1), 512, SM8>>>(
        h, HAGG, WU, bu1, nullptr, nullptr,
        U, nullptr, NN, 128, nullptr, nullptr, nullptr, nullptr, nullptr,
        SUM + 512, SSQ + 512, nullptr);
    k_fin<<<1, 128>>>(SUM + 512, SSQ + 512, gu1, bbu1, ACTA + 512, ACTC + 512, NN, 128);

    // residual outputs
    k_final<<<(NN * 128 + 255) / 256, 256>>>(h, pos, ACTA + 512, ACTC + 512, out);
}